// round 1
// baseline (speedup 1.0000x reference)
#include <cuda_runtime.h>
#include <math.h>
#include <stdint.h>

// ViewpointLoss: B=131072 rows, C=360 classes.
// loss = -sum_b( logp_b[label_b] ) / C, where logp = log_softmax(x / sum|x|)

#define NROWS 131072
#define NCLS  360
#define WARPS_PER_BLOCK 8
#define THREADS (WARPS_PER_BLOCK * 32)
#define NBLOCKS (NROWS / WARPS_PER_BLOCK)   // 16384
// 360 = 11*32 + 8  -> 12 slots per lane, slot 11 valid only for lane < 8
#define SLOTS 12
#define TAIL_LANES 8

__device__ float g_partials[NBLOCKS];

__global__ void __launch_bounds__(THREADS)
viewpoint_row_kernel(const float* __restrict__ preds,
                     const int*   __restrict__ labels)
{
    const int warp = threadIdx.x >> 5;
    const int lane = threadIdx.x & 31;
    const int row  = blockIdx.x * WARPS_PER_BLOCK + warp;

    const float* __restrict__ p = preds + (size_t)row * NCLS;

    // ---- load row into registers (coalesced, 12-deep MLP) ----
    float x[SLOTS];
#pragma unroll
    for (int k = 0; k < SLOTS - 1; k++)
        x[k] = p[lane + 32 * k];
    x[SLOTS - 1] = (lane < TAIL_LANES) ? p[lane + 32 * (SLOTS - 1)] : 0.0f;

    // ---- pass 1 (from regs): sum|x| and max(x) ----
    float asum = 0.0f;
    float mx   = -INFINITY;
#pragma unroll
    for (int k = 0; k < SLOTS - 1; k++) {
        asum += fabsf(x[k]);
        mx    = fmaxf(mx, x[k]);
    }
    if (lane < TAIL_LANES) {
        asum += fabsf(x[SLOTS - 1]);
        mx    = fmaxf(mx, x[SLOTS - 1]);
    }
#pragma unroll
    for (int o = 16; o > 0; o >>= 1) {
        asum += __shfl_xor_sync(0xffffffffu, asum, o);
        mx    = fmaxf(mx, __shfl_xor_sync(0xffffffffu, mx, o));
    }

    const float inv = __frcp_rn(asum);   // l1 > 0 almost surely for gaussian input
    const float m   = mx * inv;          // max of scaled row

    const int label = labels[row];       // uniform across warp (broadcast load)

    // ---- pass 2 (from regs): sum exp(scaled - m) and gather scaled[label] ----
    float es = 0.0f;
    float gv = 0.0f;
#pragma unroll
    for (int k = 0; k < SLOTS; k++) {
        const int  idx   = lane + 32 * k;
        const bool valid = (k < SLOTS - 1) | (lane < TAIL_LANES);
        const float s = x[k] * inv;
        if (valid) {
            es += __expf(s - m);
            if (idx == label) gv = s;
        }
    }
#pragma unroll
    for (int o = 16; o > 0; o >>= 1) {
        es += __shfl_xor_sync(0xffffffffu, es, o);
        gv += __shfl_xor_sync(0xffffffffu, gv, o);   // only one lane nonzero
    }

    // per-row contribution: -(logp[label]) = -(gv - m - log(es))
    const float contrib = -(gv - m - __logf(es));

    // ---- block reduce (8 warp leaders) -> one partial per block ----
    __shared__ float sbuf[WARPS_PER_BLOCK];
    if (lane == 0) sbuf[warp] = contrib;
    __syncthreads();
    if (threadIdx.x == 0) {
        float t = 0.0f;
#pragma unroll
        for (int i = 0; i < WARPS_PER_BLOCK; i++) t += sbuf[i];
        g_partials[blockIdx.x] = t;
    }
}

__global__ void __launch_bounds__(256)
viewpoint_reduce_kernel(float* __restrict__ out)
{
    __shared__ double sred[256];
    double acc = 0.0;
    for (int i = threadIdx.x; i < NBLOCKS; i += 256)
        acc += (double)g_partials[i];
    sred[threadIdx.x] = acc;
    __syncthreads();
    for (int s = 128; s > 0; s >>= 1) {
        if (threadIdx.x < s) sred[threadIdx.x] += sred[threadIdx.x + s];
        __syncthreads();
    }
    if (threadIdx.x == 0)
        out[0] = (float)(sred[0] / (double)NCLS);
}

extern "C" void kernel_launch(void* const* d_in, const int* in_sizes, int n_in,
                              void* d_out, int out_size)
{
    const float* preds  = (const float*)d_in[0];
    const int*   labels = (const int*)d_in[1];
    float*       out    = (float*)d_out;

    viewpoint_row_kernel<<<NBLOCKS, THREADS>>>(preds, labels);
    viewpoint_reduce_kernel<<<1, 256>>>(out);
}